// round 3
// baseline (speedup 1.0000x reference)
#include <cuda_runtime.h>
#include <cuda_fp16.h>
#include <cstdint>

// Problem dims
#define BB    128
#define TT    512
#define DIN   256
#define DH    512
#define G4    2048        // 4*DH
#define DOUT  256
#define RCTA  128         // 8 batch-group clusters x 16 col-group CTAs
#define CLSZ  16

// ---------------- static device scratch ----------------
__device__ __half g_x_h[(size_t)BB * TT * DIN];       // x fp16, [m=t*128+b][k]
__device__ __half g_wx [(size_t)G4 * DIN];            // w_x2h permuted, [p][k]
__device__ __half g_wh [(size_t)G4 * DH];             // w_h2h permuted, [p][k]
__device__ float  g_gbias[G4];                        // permuted biases
__device__ __half g_xg [(size_t)BB * TT * G4];        // xg fp16, [m][p]
__device__ float  g_hlast[BB * DH];                   // final h fp32

// permuted gate column: p = cg*128 + w4*32 + q*8 + u
__device__ __forceinline__ int gate_col(int p) {
    return ((p >> 3) & 3) * DH + (p >> 7) * 32 + (((p >> 5) & 3) << 3) + (p & 7);
}

__device__ __forceinline__ void mma16816(float& d0, float& d1, float& d2, float& d3,
                                         unsigned a0, unsigned a1, unsigned a2, unsigned a3,
                                         unsigned b0, unsigned b1) {
    asm volatile(
        "mma.sync.aligned.m16n8k16.row.col.f32.f16.f16.f32 "
        "{%0,%1,%2,%3}, {%4,%5,%6,%7}, {%8,%9}, {%0,%1,%2,%3};"
        : "+f"(d0), "+f"(d1), "+f"(d2), "+f"(d3)
        : "r"(a0), "r"(a1), "r"(a2), "r"(a3), "r"(b0), "r"(b1));
}

__device__ __forceinline__ float sigm(float x) { return 1.0f / (1.0f + __expf(-x)); }
__device__ __forceinline__ float tanh_a(float x) {
    x = fminf(fmaxf(x, -15.f), 15.f);
    float e = __expf(2.f * x);
    return (e - 1.f) / (e + 1.f);
}
__device__ __forceinline__ float lstm_cell(float zi, float zf, float zg, float zo, float& c) {
    float i = sigm(zi), f = sigm(zf), gg = tanh_a(zg), o = sigm(zo);
    c = fmaf(c, f, i * gg);
    return o * tanh_a(c);
}

// ---------------- cluster PTX helpers ----------------
__device__ __forceinline__ uint32_t smem_u32(const void* p) {
    uint32_t a;
    asm("{ .reg .u64 t; cvta.to.shared.u64 t, %1; cvt.u32.u64 %0, t; }" : "=r"(a) : "l"(p));
    return a;
}
__device__ __forceinline__ uint32_t cluster_rank() {
    uint32_t r; asm("mov.u32 %0, %%cluster_ctarank;" : "=r"(r)); return r;
}
__device__ __forceinline__ uint32_t mapa_u32(uint32_t local, uint32_t rank) {
    uint32_t a;
    asm("mapa.shared::cluster.u32 %0, %1, %2;" : "=r"(a) : "r"(local), "r"(rank));
    return a;
}
__device__ __forceinline__ void mbar_init(uint32_t a, uint32_t cnt) {
    asm volatile("mbarrier.init.shared.b64 [%0], %1;" :: "r"(a), "r"(cnt) : "memory");
}
__device__ __forceinline__ void mbar_arrive_expect_tx(uint32_t a, uint32_t tx) {
    asm volatile("mbarrier.arrive.expect_tx.shared::cta.b64 _, [%0], %1;"
                 :: "r"(a), "r"(tx) : "memory");
}
__device__ __forceinline__ void mbar_arrive_remote(uint32_t a) {
    asm volatile("mbarrier.arrive.release.cluster.shared::cluster.b64 _, [%0];"
                 :: "r"(a) : "memory");
}
__device__ __forceinline__ void mbar_wait(uint32_t a, int parity) {
    asm volatile(
        "{\n\t.reg .pred P;\n\t"
        "WL_%=:\n\t"
        "mbarrier.try_wait.parity.acquire.cluster.shared::cta.b64 P, [%0], %1;\n\t"
        "@P bra WD_%=;\n\t"
        "bra WL_%=;\n\t"
        "WD_%=:\n\t}"
        :: "r"(a), "r"(parity) : "memory");
}
__device__ __forceinline__ void st_async_u32(uint32_t addr, unsigned v, uint32_t rmbar) {
    asm volatile("st.async.shared::cluster.mbarrier::complete_tx::bytes.b32 [%0], %1, [%2];"
                 :: "r"(addr), "r"(v), "r"(rmbar) : "memory");
}
__device__ __forceinline__ void cluster_sync_() {
    asm volatile("barrier.cluster.arrive.aligned;" ::: "memory");
    asm volatile("barrier.cluster.wait.aligned;" ::: "memory");
}

// ---------------- prep kernels ----------------
__global__ void prep_x_kernel(const float* __restrict__ x) {
    size_t idx = (size_t)blockIdx.x * 256 + threadIdx.x;
    int k = idx & 255;
    int m = (int)(idx >> 8);
    int t = m >> 7, b = m & 127;
    g_x_h[idx] = __float2half_rn(x[((size_t)b * TT + t) * DIN + k]);
}

__global__ void prep_w_kernel(const float* __restrict__ w_x2h, const float* __restrict__ b_x2h,
                              const float* __restrict__ w_h2h, const float* __restrict__ b_h2h) {
    int idx = blockIdx.x * 256 + threadIdx.x;   // 1,048,576 = 2048*512
    {
        int p = idx >> 9, k = idx & 511;
        g_wh[idx] = __float2half_rn(w_h2h[(size_t)k * G4 + gate_col(p)]);
    }
    if (idx < G4 * DIN) {
        int p = idx >> 8, k = idx & 255;
        g_wx[idx] = __float2half_rn(w_x2h[(size_t)k * G4 + gate_col(p)]);
    }
    if (idx < G4) {
        int gc = gate_col(idx);
        g_gbias[idx] = b_x2h[gc] + b_h2h[gc];
    }
}

// ---------------- GEMM1: xg = x @ wx + bias (fp16 out) ----------------
#define G1_SMEM ((128 * 264 + 64 * 264) * 2)
__global__ __launch_bounds__(256, 1) void gemm1_kernel() {
    extern __shared__ __half sm[];
    __half* x_sm = sm;                 // 128 x 264
    __half* w_sm = sm + 128 * 264;     // 64  x 264
    const int tid = threadIdx.x;
    const int m0 = blockIdx.y * 128, n0 = blockIdx.x * 64;

    const uint4* xs = (const uint4*)g_x_h;
    #pragma unroll 4
    for (int i = tid; i < 4096; i += 256) {
        int r = i >> 5, k8 = (i & 31) << 3;
        *(uint4*)&x_sm[r * 264 + k8] = xs[(size_t)(m0 + r) * 32 + (i & 31)];
    }
    const uint4* ws = (const uint4*)g_wx;
    #pragma unroll 4
    for (int i = tid; i < 2048; i += 256) {
        int c = i >> 5, k8 = (i & 31) << 3;
        *(uint4*)&w_sm[c * 264 + k8] = ws[(size_t)(n0 + c) * 32 + (i & 31)];
    }
    __syncthreads();

    const int w = tid >> 5, lane = tid & 31, g = lane >> 2, q = lane & 3;
    const int r0 = 16 * w + g;
    float acc[8][4];
    #pragma unroll
    for (int nt = 0; nt < 8; nt++) { acc[nt][0] = acc[nt][1] = acc[nt][2] = acc[nt][3] = 0.f; }

    #pragma unroll 4
    for (int kt = 0; kt < 16; kt++) {
        int k0 = kt * 16 + 2 * q;
        unsigned a0 = *(const unsigned*)&x_sm[r0 * 264 + k0];
        unsigned a1 = *(const unsigned*)&x_sm[(r0 + 8) * 264 + k0];
        unsigned a2 = *(const unsigned*)&x_sm[r0 * 264 + k0 + 8];
        unsigned a3 = *(const unsigned*)&x_sm[(r0 + 8) * 264 + k0 + 8];
        #pragma unroll
        for (int nt = 0; nt < 8; nt++) {
            unsigned b0 = *(const unsigned*)&w_sm[(8 * nt + g) * 264 + k0];
            unsigned b1 = *(const unsigned*)&w_sm[(8 * nt + g) * 264 + k0 + 8];
            mma16816(acc[nt][0], acc[nt][1], acc[nt][2], acc[nt][3], a0, a1, a2, a3, b0, b1);
        }
    }
    #pragma unroll
    for (int nt = 0; nt < 8; nt++) {
        int p = n0 + 8 * nt + 2 * q;
        float2 gb = *(const float2*)&g_gbias[p];
        *(__half2*)&g_xg[(size_t)(m0 + r0) * G4 + p] =
            __floats2half2_rn(acc[nt][0] + gb.x, acc[nt][1] + gb.y);
        *(__half2*)&g_xg[(size_t)(m0 + r0 + 8) * G4 + p] =
            __floats2half2_rn(acc[nt][2] + gb.x, acc[nt][3] + gb.y);
    }
}

// ---------------- persistent recurrent kernel (16-CTA DSMEM clusters) ----------------
#define W_HALVES   (128 * 520)
#define HB_HALVES  (16 * 520)                 // one h buffer
#define W_BYTES    (W_HALVES * 2)             // 133120
#define H_BYTES    (2 * HB_HALVES * 2)        // 33280
#define RED_BYTES  (128 * 17 * 4)             // 8704
#define MBAR_OFF   (W_BYTES + H_BYTES + RED_BYTES)   // 175104 (8-aligned)
#define REC_SMEM   (MBAR_OFF + 64)
#define HTX_BYTES  (16 * DH * 2)              // 16384 bytes per step per consumer

__global__ __launch_bounds__(256, 1) void rec_kernel() {
    extern __shared__ unsigned char smraw[];
    __half* w_sm = (__half*)smraw;                          // 128 x 520
    __half* h_sm = (__half*)(smraw + W_BYTES);              // [2][16][520]
    float*  red  = (float*)(smraw + W_BYTES + H_BYTES);     // [128][17]

    const uint32_t sbase  = smem_u32(smraw);
    const uint32_t h_base = sbase + W_BYTES;
    const uint32_t mb     = sbase + MBAR_OFF;   // full0,full1,empty0,empty1 (8B each)

    const int tid = threadIdx.x;
    const int bg = blockIdx.x >> 4;
    const uint32_t cg = cluster_rank();
    const int w = tid >> 5, lane = tid & 31;
    const int g = lane >> 2, q = lane & 3;
    const int w4 = w & 3, kh = w >> 2;
    const int r0 = g, r1 = g + 8;

    // stationary weights -> smem
    const uint4* ws = (const uint4*)(g_wh + (size_t)cg * 128 * DH);
    #pragma unroll 8
    for (int i = tid; i < 8192; i += 256) {
        int c = i >> 6, k8 = (i & 63) << 3;
        *(uint4*)&w_sm[c * 520 + k8] = ws[i];
    }

    if (tid == 0) {
        mbar_init(mb + 0, 1);    // full0: 1 arrival (consumer expect_tx) + tx bytes
        mbar_init(mb + 8, 1);    // full1
        mbar_init(mb + 16, 16);  // empty0: 16 consumer arrivals
        mbar_init(mb + 24, 16);  // empty1
        mbar_arrive_expect_tx(mb + 0, HTX_BYTES);   // arm full0 (first use: t=2)
        mbar_arrive_expect_tx(mb + 8, HTX_BYTES);   // arm full1 (first use: t=1)
        asm volatile("fence.mbarrier_init.release.cluster;" ::: "memory");
    }
    __syncthreads();
    cluster_sync_();

    // peer base addresses (for h_base); any peer smem addr = pb[r] + (local - h_base)
    uint32_t pb[CLSZ];
    #pragma unroll
    for (int r = 0; r < CLSZ; r++) pb[r] = mapa_u32(h_base, (uint32_t)r);
    const uint32_t mb_delta = mb - h_base;

    int fpar[2] = {0, 0}, epar[2] = {0, 0};
    float c00 = 0.f, c01 = 0.f, c10 = 0.f, c11 = 0.f;

    for (int t = 0; t < TT; t++) {
        const int s = t & 1;

        // xg prefetch (warps 0-3), fp16
        float2 xf0[4], xf1[4];
        if (kh == 0) {
            const __half* x0 = g_xg + (size_t)(t * BB + bg * 16 + r0) * G4
                               + cg * 128 + w4 * 32 + 2 * q;
            const __half* x1 = x0 + (size_t)8 * G4;
            #pragma unroll
            for (int nt = 0; nt < 4; nt++) {
                unsigned u0 = __ldcg((const unsigned*)(x0 + nt * 8));
                unsigned u1 = __ldcg((const unsigned*)(x1 + nt * 8));
                xf0[nt] = __half22float2(*(__half2*)&u0);
                xf1[nt] = __half22float2(*(__half2*)&u1);
            }
        }

        float acc[4][4];
        #pragma unroll
        for (int nt = 0; nt < 4; nt++) { acc[nt][0] = acc[nt][1] = acc[nt][2] = acc[nt][3] = 0.f; }

        if (t > 0) {
            if (tid == 0) { mbar_wait(mb + s * 8, fpar[s]); fpar[s] ^= 1; }
            __syncthreads();

            const __half* hs = h_sm + s * HB_HALVES;
            #pragma unroll
            for (int kt = 0; kt < 16; kt++) {
                int k0 = kh * 256 + kt * 16 + 2 * q;
                unsigned a0 = *(const unsigned*)&hs[r0 * 520 + k0];
                unsigned a1 = *(const unsigned*)&hs[r1 * 520 + k0];
                unsigned a2 = *(const unsigned*)&hs[r0 * 520 + k0 + 8];
                unsigned a3 = *(const unsigned*)&hs[r1 * 520 + k0 + 8];
                #pragma unroll
                for (int nt = 0; nt < 4; nt++) {
                    const __half* wb = &w_sm[(w4 * 32 + nt * 8 + g) * 520 + k0];
                    unsigned b0 = *(const unsigned*)wb;
                    unsigned b1 = *(const unsigned*)(wb + 8);
                    mma16816(acc[nt][0], acc[nt][1], acc[nt][2], acc[nt][3], a0, a1, a2, a3, b0, b1);
                }
            }

            if (kh == 1) {
                float* rp = red + (w4 * 32 + lane) * 17;
                #pragma unroll
                for (int nt = 0; nt < 4; nt++) {
                    #pragma unroll
                    for (int e = 0; e < 4; e++) rp[nt * 4 + e] = acc[nt][e];
                }
            }
            __syncthreads();     // h_sm[s] reads + red writes complete
            if (kh == 0) {
                const float* rp = red + (w4 * 32 + lane) * 17;
                #pragma unroll
                for (int nt = 0; nt < 4; nt++) {
                    #pragma unroll
                    for (int e = 0; e < 4; e++) acc[nt][e] += rp[nt * 4 + e];
                }
            }
            // re-arm full[s] for use t+2; notify peers h_sm[s] is consumable again
            if (tid == 0) mbar_arrive_expect_tx(mb + s * 8, HTX_BYTES);
            if (tid < CLSZ) mbar_arrive_remote(pb[tid] + mb_delta + 16 + s * 8);
        }

        float h00, h01, h10, h11;
        if (kh == 0) {
            h00 = lstm_cell(acc[0][0] + xf0[0].x, acc[1][0] + xf0[1].x,
                            acc[2][0] + xf0[2].x, acc[3][0] + xf0[3].x, c00);
            h01 = lstm_cell(acc[0][1] + xf0[0].y, acc[1][1] + xf0[1].y,
                            acc[2][1] + xf0[2].y, acc[3][1] + xf0[3].y, c01);
            h10 = lstm_cell(acc[0][2] + xf1[0].x, acc[1][2] + xf1[1].x,
                            acc[2][2] + xf1[2].x, acc[3][2] + xf1[3].x, c10);
            h11 = lstm_cell(acc[0][3] + xf1[0].y, acc[1][3] + xf1[1].y,
                            acc[2][3] + xf1[2].y, acc[3][3] + xf1[3].y, c11);
            if (t == TT - 1) {
                int row0 = bg * 16 + r0, row1 = row0 + 8;
                int hoff = (int)cg * 32 + w4 * 8 + 2 * q;
                *(float2*)&g_hlast[row0 * DH + hoff] = make_float2(h00, h01);
                *(float2*)&g_hlast[row1 * DH + hoff] = make_float2(h10, h11);
            }
        }

        if (t < TT - 1) {
            const int s2 = (t + 1) & 1;
            if (t + 1 >= 3) {
                if (tid == 0) { mbar_wait(mb + 16 + s2 * 8, epar[s2]); epar[s2] ^= 1; }
            }
            __syncthreads();   // gate stores on empty-wait
            if (kh == 0) {
                unsigned v0, v1;
                { __half2 t2 = __floats2half2_rn(h00, h01); v0 = *(unsigned*)&t2; }
                { __half2 t2 = __floats2half2_rn(h10, h11); v1 = *(unsigned*)&t2; }
                const uint32_t col = (uint32_t)cg * 32 + w4 * 8 + 2 * q;
                const uint32_t off0 = (uint32_t)(s2 * HB_HALVES + r0 * 520 + col) * 2;
                const uint32_t off1 = (uint32_t)(s2 * HB_HALVES + r1 * 520 + col) * 2;
                const uint32_t mdel = mb_delta + s2 * 8;   // peer full[s2]
                #pragma unroll
                for (int r = 0; r < CLSZ; r++) {
                    st_async_u32(pb[r] + off0, v0, pb[r] + mdel);
                    st_async_u32(pb[r] + off1, v1, pb[r] + mdel);
                }
            }
        }
    }
    cluster_sync_();
}

// ---------------- final FC ----------------
__global__ void fc_kernel(const float* __restrict__ w_fc, const float* __restrict__ b_fc,
                          float* __restrict__ out) {
    __shared__ float hs[DH];
    int b = blockIdx.x, o = threadIdx.x;
    for (int i = o; i < DH; i += 256) hs[i] = g_hlast[b * DH + i];
    __syncthreads();
    float acc = b_fc[o];
    #pragma unroll 8
    for (int k = 0; k < DH; k++) acc = fmaf(hs[k], w_fc[(size_t)k * DOUT + o], acc);
    out[b * DOUT + o] = acc;
}

// ---------------- launch ----------------
extern "C" void kernel_launch(void* const* d_in, const int* in_sizes, int n_in,
                              void* d_out, int out_size) {
    (void)in_sizes; (void)n_in; (void)out_size;
    const float* x     = (const float*)d_in[0];
    const float* w_x2h = (const float*)d_in[1];
    const float* b_x2h = (const float*)d_in[2];
    const float* w_h2h = (const float*)d_in[3];
    const float* b_h2h = (const float*)d_in[4];
    const float* w_fc  = (const float*)d_in[5];
    const float* b_fc  = (const float*)d_in[6];
    float* out = (float*)d_out;

    cudaFuncSetAttribute(gemm1_kernel, cudaFuncAttributeMaxDynamicSharedMemorySize, G1_SMEM);
    cudaFuncSetAttribute(rec_kernel,   cudaFuncAttributeMaxDynamicSharedMemorySize, REC_SMEM);
    cudaFuncSetAttribute(rec_kernel,   cudaFuncAttributeNonPortableClusterSizeAllowed, 1);

    prep_x_kernel<<<65536, 256>>>(x);
    prep_w_kernel<<<4096, 256>>>(w_x2h, b_x2h, w_h2h, b_h2h);
    gemm1_kernel<<<dim3(32, 512), 256, G1_SMEM>>>();

    cudaLaunchConfig_t cfg = {};
    cfg.gridDim = dim3(RCTA, 1, 1);
    cfg.blockDim = dim3(256, 1, 1);
    cfg.dynamicSmemBytes = REC_SMEM;
    cfg.stream = 0;
    cudaLaunchAttribute at[1];
    at[0].id = cudaLaunchAttributeClusterDimension;
    at[0].val.clusterDim.x = CLSZ; at[0].val.clusterDim.y = 1; at[0].val.clusterDim.z = 1;
    cfg.attrs = at; cfg.numAttrs = 1;
    cudaLaunchKernelEx(&cfg, rec_kernel);

    fc_kernel<<<BB, 256>>>(w_fc, b_fc, out);
}

// round 4
// speedup vs baseline: 1.7228x; 1.7228x over previous
#include <cuda_runtime.h>
#include <cuda_fp16.h>
#include <cstdint>

// Problem dims
#define BB    128
#define TT    512
#define DIN   256
#define DH    512
#define G4    2048        // 4*DH
#define DOUT  256
#define RCTA  128         // 8 batch-group clusters x 16 col-group CTAs
#define CLSZ  16

// ---------------- static device scratch ----------------
__device__ __half g_x_h[(size_t)BB * TT * DIN];       // x fp16, [m=t*128+b][k]
__device__ __half g_wx [(size_t)G4 * DIN];            // w_x2h permuted, [p][k]
__device__ __half g_wh [(size_t)G4 * DH];             // w_h2h permuted, [p][k]
__device__ float  g_gbias[G4];                        // permuted biases
__device__ __half g_xg [(size_t)BB * TT * G4];        // xg fp16, [m][p]
__device__ __half g_hbuf[2][BB * DH];                 // double-buffered h (fp16, L2)
__device__ float  g_hlast[BB * DH];                   // final h fp32

// permuted gate column: p = cg*128 + w4*32 + q*8 + u
__device__ __forceinline__ int gate_col(int p) {
    return ((p >> 3) & 3) * DH + (p >> 7) * 32 + (((p >> 5) & 3) << 3) + (p & 7);
}

__device__ __forceinline__ void mma16816(float& d0, float& d1, float& d2, float& d3,
                                         unsigned a0, unsigned a1, unsigned a2, unsigned a3,
                                         unsigned b0, unsigned b1) {
    asm volatile(
        "mma.sync.aligned.m16n8k16.row.col.f32.f16.f16.f32 "
        "{%0,%1,%2,%3}, {%4,%5,%6,%7}, {%8,%9}, {%0,%1,%2,%3};"
        : "+f"(d0), "+f"(d1), "+f"(d2), "+f"(d3)
        : "r"(a0), "r"(a1), "r"(a2), "r"(a3), "r"(b0), "r"(b1));
}

__device__ __forceinline__ float sigm(float x) { return 1.0f / (1.0f + __expf(-x)); }
__device__ __forceinline__ float tanh_a(float x) {
    x = fminf(fmaxf(x, -15.f), 15.f);
    float e = __expf(2.f * x);
    return (e - 1.f) / (e + 1.f);
}
__device__ __forceinline__ float lstm_cell(float zi, float zf, float zg, float zo, float& c) {
    float i = sigm(zi), f = sigm(zf), gg = tanh_a(zg), o = sigm(zo);
    c = fmaf(c, f, i * gg);
    return o * tanh_a(c);
}

// ---------------- cluster PTX helpers ----------------
__device__ __forceinline__ uint32_t smem_u32(const void* p) {
    uint32_t a;
    asm("{ .reg .u64 t; cvta.to.shared.u64 t, %1; cvt.u32.u64 %0, t; }" : "=r"(a) : "l"(p));
    return a;
}
__device__ __forceinline__ uint32_t cluster_rank() {
    uint32_t r; asm("mov.u32 %0, %%cluster_ctarank;" : "=r"(r)); return r;
}
__device__ __forceinline__ uint32_t mapa_u32(uint32_t local, uint32_t rank) {
    uint32_t a;
    asm("mapa.shared::cluster.u32 %0, %1, %2;" : "=r"(a) : "r"(local), "r"(rank));
    return a;
}
__device__ __forceinline__ void mbar_init(uint32_t a, uint32_t cnt) {
    asm volatile("mbarrier.init.shared.b64 [%0], %1;" :: "r"(a), "r"(cnt) : "memory");
}
__device__ __forceinline__ void mbar_arrive_remote(uint32_t a) {
    asm volatile("mbarrier.arrive.release.cluster.shared::cluster.b64 _, [%0];"
                 :: "r"(a) : "memory");
}
__device__ __forceinline__ void mbar_wait(uint32_t a, int parity) {
    asm volatile(
        "{\n\t.reg .pred P;\n\t"
        "WL_%=:\n\t"
        "mbarrier.try_wait.parity.acquire.cluster.shared::cta.b64 P, [%0], %1, 0x989680;\n\t"
        "@P bra WD_%=;\n\t"
        "bra WL_%=;\n\t"
        "WD_%=:\n\t}"
        :: "r"(a), "r"(parity) : "memory");
}
__device__ __forceinline__ void cluster_sync_() {
    asm volatile("barrier.cluster.arrive.aligned;" ::: "memory");
    asm volatile("barrier.cluster.wait.aligned;" ::: "memory");
}

// ---------------- prep kernels ----------------
__global__ void prep_x_kernel(const float* __restrict__ x) {
    size_t idx = (size_t)blockIdx.x * 256 + threadIdx.x;
    int k = idx & 255;
    int m = (int)(idx >> 8);
    int t = m >> 7, b = m & 127;
    g_x_h[idx] = __float2half_rn(x[((size_t)b * TT + t) * DIN + k]);
}

__global__ void prep_w_kernel(const float* __restrict__ w_x2h, const float* __restrict__ b_x2h,
                              const float* __restrict__ w_h2h, const float* __restrict__ b_h2h) {
    int idx = blockIdx.x * 256 + threadIdx.x;   // 1,048,576 = 2048*512
    {
        int p = idx >> 9, k = idx & 511;
        g_wh[idx] = __float2half_rn(w_h2h[(size_t)k * G4 + gate_col(p)]);
    }
    if (idx < G4 * DIN) {
        int p = idx >> 8, k = idx & 255;
        g_wx[idx] = __float2half_rn(w_x2h[(size_t)k * G4 + gate_col(p)]);
    }
    if (idx < G4) {
        int gc = gate_col(idx);
        g_gbias[idx] = b_x2h[gc] + b_h2h[gc];
    }
}

// ---------------- GEMM1: xg = x @ wx + bias (fp16 out) ----------------
#define G1_SMEM ((128 * 264 + 64 * 264) * 2)
__global__ __launch_bounds__(256, 1) void gemm1_kernel() {
    extern __shared__ __half sm[];
    __half* x_sm = sm;                 // 128 x 264
    __half* w_sm = sm + 128 * 264;     // 64  x 264
    const int tid = threadIdx.x;
    const int m0 = blockIdx.y * 128, n0 = blockIdx.x * 64;

    const uint4* xs = (const uint4*)g_x_h;
    #pragma unroll 4
    for (int i = tid; i < 4096; i += 256) {
        int r = i >> 5, k8 = (i & 31) << 3;
        *(uint4*)&x_sm[r * 264 + k8] = xs[(size_t)(m0 + r) * 32 + (i & 31)];
    }
    const uint4* ws = (const uint4*)g_wx;
    #pragma unroll 4
    for (int i = tid; i < 2048; i += 256) {
        int c = i >> 5, k8 = (i & 31) << 3;
        *(uint4*)&w_sm[c * 264 + k8] = ws[(size_t)(n0 + c) * 32 + (i & 31)];
    }
    __syncthreads();

    const int w = tid >> 5, lane = tid & 31, g = lane >> 2, q = lane & 3;
    const int r0 = 16 * w + g;
    float acc[8][4];
    #pragma unroll
    for (int nt = 0; nt < 8; nt++) { acc[nt][0] = acc[nt][1] = acc[nt][2] = acc[nt][3] = 0.f; }

    #pragma unroll 4
    for (int kt = 0; kt < 16; kt++) {
        int k0 = kt * 16 + 2 * q;
        unsigned a0 = *(const unsigned*)&x_sm[r0 * 264 + k0];
        unsigned a1 = *(const unsigned*)&x_sm[(r0 + 8) * 264 + k0];
        unsigned a2 = *(const unsigned*)&x_sm[r0 * 264 + k0 + 8];
        unsigned a3 = *(const unsigned*)&x_sm[(r0 + 8) * 264 + k0 + 8];
        #pragma unroll
        for (int nt = 0; nt < 8; nt++) {
            unsigned b0 = *(const unsigned*)&w_sm[(8 * nt + g) * 264 + k0];
            unsigned b1 = *(const unsigned*)&w_sm[(8 * nt + g) * 264 + k0 + 8];
            mma16816(acc[nt][0], acc[nt][1], acc[nt][2], acc[nt][3], a0, a1, a2, a3, b0, b1);
        }
    }
    #pragma unroll
    for (int nt = 0; nt < 8; nt++) {
        int p = n0 + 8 * nt + 2 * q;
        float2 gb = *(const float2*)&g_gbias[p];
        *(__half2*)&g_xg[(size_t)(m0 + r0) * G4 + p] =
            __floats2half2_rn(acc[nt][0] + gb.x, acc[nt][1] + gb.y);
        *(__half2*)&g_xg[(size_t)(m0 + r0 + 8) * G4 + p] =
            __floats2half2_rn(acc[nt][2] + gb.x, acc[nt][3] + gb.y);
    }
}

// ---------------- persistent recurrent kernel ----------------
// 128 CTAs = 8 batch-group clusters x 16 col-group CTAs.
// Data via L2 (ldcg/stcg), signaling via cluster mbarriers (remote arrives).
#define W_HALVES   (128 * 520)
#define HS_HALVES  (16 * 520)
#define W_BYTES    (W_HALVES * 2)             // 133120
#define HS_BYTES   (HS_HALVES * 2)            // 16640
#define RED_BYTES  (128 * 17 * 4)             // 8704
#define MBAR_OFF   (W_BYTES + HS_BYTES + RED_BYTES)   // 158464 (8-aligned)
#define REC_SMEM   (MBAR_OFF + 64)

__global__ __launch_bounds__(256, 1) void rec_kernel() {
    extern __shared__ unsigned char smraw[];
    __half* w_sm = (__half*)smraw;                          // 128 x 520
    __half* h_sm = (__half*)(smraw + W_BYTES);              // 16 x 520
    float*  red  = (float*)(smraw + W_BYTES + HS_BYTES);    // [128][17]

    const uint32_t sbase = smem_u32(smraw);
    const uint32_t mb    = sbase + MBAR_OFF;   // full0 @ +0, full1 @ +8

    const int tid = threadIdx.x;
    const int bg = blockIdx.x >> 4;
    const uint32_t cg = cluster_rank();
    const int w = tid >> 5, lane = tid & 31;
    const int g = lane >> 2, q = lane & 3;
    const int w4 = w & 3, kh = w >> 2;
    const int r0 = g, r1 = g + 8;

    // stationary weights -> smem (once)
    const uint4* ws = (const uint4*)(g_wh + (size_t)cg * 128 * DH);
    #pragma unroll 8
    for (int i = tid; i < 8192; i += 256) {
        int c = i >> 6, k8 = (i & 63) << 3;
        *(uint4*)&w_sm[c * 520 + k8] = ws[i];
    }

    if (tid == 0) {
        mbar_init(mb + 0, CLSZ);   // full0 (h at even t)
        mbar_init(mb + 8, CLSZ);   // full1 (h at odd t)
        asm volatile("fence.mbarrier_init.release.cluster;" ::: "memory");
    }
    __syncthreads();
    cluster_sync_();

    // thread tid<16 signals peer rank 'tid'
    uint32_t peer_mb = 0;
    if (tid < CLSZ) peer_mb = mapa_u32(mb, (uint32_t)tid);

    int fpar[2] = {0, 0};
    float c00 = 0.f, c01 = 0.f, c10 = 0.f, c11 = 0.f;

    for (int t = 0; t < TT; t++) {
        const int s = t & 1;

        // xg prefetch (warps 0-3), fp16 — in flight during the wait
        float2 xf0[4], xf1[4];
        if (kh == 0) {
            const __half* x0 = g_xg + (size_t)(t * BB + bg * 16 + r0) * G4
                               + cg * 128 + w4 * 32 + 2 * q;
            const __half* x1 = x0 + (size_t)8 * G4;
            #pragma unroll
            for (int nt = 0; nt < 4; nt++) {
                __half2 u0 = __ldg((const __half2*)(x0 + nt * 8));
                __half2 u1 = __ldg((const __half2*)(x1 + nt * 8));
                xf0[nt] = __half22float2(u0);
                xf1[nt] = __half22float2(u1);
            }
        }

        float acc[4][4];
        #pragma unroll
        for (int nt = 0; nt < 4; nt++) { acc[nt][0] = acc[nt][1] = acc[nt][2] = acc[nt][3] = 0.f; }

        if (t > 0) {
            // HW-sleep wait: all 16 peers published h(t) to L2
            if (tid == 0) { mbar_wait(mb + s * 8, fpar[s]); fpar[s] ^= 1; }
            __syncthreads();

            // h(t) rows [bg*16,+16) -> smem (L2-coherent)
            const uint4* hsrc = (const uint4*)(g_hbuf[s]) + (size_t)bg * 16 * (DH / 8);
            #pragma unroll
            for (int it = 0; it < 4; it++) {
                int i = tid + it * 256;                  // 1024 uint4
                int m = i >> 6, k8 = (i & 63) << 3;
                uint4 v = __ldcg(hsrc + i);
                *(uint4*)&h_sm[m * 520 + k8] = v;
            }
            __syncthreads();

            // gates += h @ W   (M=16, per warp N=32, split-K halves)
            #pragma unroll
            for (int kt = 0; kt < 16; kt++) {
                int k0 = kh * 256 + kt * 16 + 2 * q;
                unsigned a0 = *(const unsigned*)&h_sm[r0 * 520 + k0];
                unsigned a1 = *(const unsigned*)&h_sm[r1 * 520 + k0];
                unsigned a2 = *(const unsigned*)&h_sm[r0 * 520 + k0 + 8];
                unsigned a3 = *(const unsigned*)&h_sm[r1 * 520 + k0 + 8];
                #pragma unroll
                for (int nt = 0; nt < 4; nt++) {
                    const __half* wb = &w_sm[(w4 * 32 + nt * 8 + g) * 520 + k0];
                    unsigned b0 = *(const unsigned*)wb;
                    unsigned b1 = *(const unsigned*)(wb + 8);
                    mma16816(acc[nt][0], acc[nt][1], acc[nt][2], acc[nt][3], a0, a1, a2, a3, b0, b1);
                }
            }

            // split-K reduction: warps 4-7 hand partials to warps 0-3
            if (kh == 1) {
                float* rp = red + (w4 * 32 + lane) * 17;
                #pragma unroll
                for (int nt = 0; nt < 4; nt++) {
                    #pragma unroll
                    for (int e = 0; e < 4; e++) rp[nt * 4 + e] = acc[nt][e];
                }
            }
            __syncthreads();
            if (kh == 0) {
                const float* rp = red + (w4 * 32 + lane) * 17;
                #pragma unroll
                for (int nt = 0; nt < 4; nt++) {
                    #pragma unroll
                    for (int e = 0; e < 4; e++) acc[nt][e] += rp[nt * 4 + e];
                }
            }
        }

        if (kh == 0) {
            float h00 = lstm_cell(acc[0][0] + xf0[0].x, acc[1][0] + xf0[1].x,
                                  acc[2][0] + xf0[2].x, acc[3][0] + xf0[3].x, c00);
            float h01 = lstm_cell(acc[0][1] + xf0[0].y, acc[1][1] + xf0[1].y,
                                  acc[2][1] + xf0[2].y, acc[3][1] + xf0[3].y, c01);
            float h10 = lstm_cell(acc[0][2] + xf1[0].x, acc[1][2] + xf1[1].x,
                                  acc[2][2] + xf1[2].x, acc[3][2] + xf1[3].x, c10);
            float h11 = lstm_cell(acc[0][3] + xf1[0].y, acc[1][3] + xf1[1].y,
                                  acc[2][3] + xf1[2].y, acc[3][3] + xf1[3].y, c11);

            int row0 = bg * 16 + r0, row1 = row0 + 8;
            int hoff = (int)cg * 32 + w4 * 8 + 2 * q;
            if (t < TT - 1) {
                __half* hd = g_hbuf[(t + 1) & 1];
                __half2 v0 = __floats2half2_rn(h00, h01);
                __half2 v1 = __floats2half2_rn(h10, h11);
                __stcg((__half2*)(hd + row0 * DH + hoff), v0);
                __stcg((__half2*)(hd + row1 * DH + hoff), v1);
            } else {
                *(float2*)&g_hlast[row0 * DH + hoff] = make_float2(h00, h01);
                *(float2*)&g_hlast[row1 * DH + hoff] = make_float2(h10, h11);
            }
        }

        if (t < TT - 1) {
            __threadfence();        // drain h(t+1) stores to L2 (release)
            __syncthreads();        // all warps' stores fenced
            if (tid < CLSZ) mbar_arrive_remote(peer_mb + ((t + 1) & 1) * 8);
        }
    }
    cluster_sync_();
}

// ---------------- final FC ----------------
__global__ void fc_kernel(const float* __restrict__ w_fc, const float* __restrict__ b_fc,
                          float* __restrict__ out) {
    __shared__ float hs[DH];
    int b = blockIdx.x, o = threadIdx.x;
    for (int i = o; i < DH; i += 256) hs[i] = g_hlast[b * DH + i];
    __syncthreads();
    float acc = b_fc[o];
    #pragma unroll 8
    for (int k = 0; k < DH; k++) acc = fmaf(hs[k], w_fc[(size_t)k * DOUT + o], acc);
    out[b * DOUT + o] = acc;
}

// ---------------- launch ----------------
extern "C" void kernel_launch(void* const* d_in, const int* in_sizes, int n_in,
                              void* d_out, int out_size) {
    (void)in_sizes; (void)n_in; (void)out_size;
    const float* x     = (const float*)d_in[0];
    const float* w_x2h = (const float*)d_in[1];
    const float* b_x2h = (const float*)d_in[2];
    const float* w_h2h = (const float*)d_in[3];
    const float* b_h2h = (const float*)d_in[4];
    const float* w_fc  = (const float*)d_in[5];
    const float* b_fc  = (const float*)d_in[6];
    float* out = (float*)d_out;

    cudaFuncSetAttribute(gemm1_kernel, cudaFuncAttributeMaxDynamicSharedMemorySize, G1_SMEM);
    cudaFuncSetAttribute(rec_kernel,   cudaFuncAttributeMaxDynamicSharedMemorySize, REC_SMEM);
    cudaFuncSetAttribute(rec_kernel,   cudaFuncAttributeNonPortableClusterSizeAllowed, 1);

    prep_x_kernel<<<65536, 256>>>(x);
    prep_w_kernel<<<4096, 256>>>(w_x2h, b_x2h, w_h2h, b_h2h);
    gemm1_kernel<<<dim3(32, 512), 256, G1_SMEM>>>();

    cudaLaunchConfig_t cfg = {};
    cfg.gridDim = dim3(RCTA, 1, 1);
    cfg.blockDim = dim3(256, 1, 1);
    cfg.dynamicSmemBytes = REC_SMEM;
    cfg.stream = 0;
    cudaLaunchAttribute at[1];
    at[0].id = cudaLaunchAttributeClusterDimension;
    at[0].val.clusterDim.x = CLSZ; at[0].val.clusterDim.y = 1; at[0].val.clusterDim.z = 1;
    cfg.attrs = at; cfg.numAttrs = 1;
    cudaLaunchKernelEx(&cfg, rec_kernel);

    fc_kernel<<<BB, 256>>>(w_fc, b_fc, out);
}

// round 6
// speedup vs baseline: 1.7559x; 1.0192x over previous
#include <cuda_runtime.h>
#include <cuda_fp16.h>
#include <cstdint>

// Problem dims
#define BB    128
#define TT    512
#define DIN   256
#define DH    512
#define G4    2048        // 4*DH
#define DOUT  256
#define RCTA  128         // 8 batch-group clusters x 16 col-group CTAs
#define CLSZ  16

// ---------------- static device scratch ----------------
__device__ __half g_x_h[(size_t)BB * TT * DIN];       // x fp16, [m=t*128+b][k]
__device__ __half g_wx [(size_t)G4 * DIN];            // w_x2h permuted, [p][k]
__device__ __half g_wh [(size_t)G4 * DH];             // w_h2h permuted, [p][k]
__device__ float  g_gbias[G4];                        // permuted biases
__device__ __half g_xg [(size_t)BB * TT * G4];        // xg fp16, [m][p]
__device__ float  g_hlast[BB * DH];                   // final h fp32

// permuted gate column: p = cg*128 + w4*32 + q*8 + u
__device__ __forceinline__ int gate_col(int p) {
    return ((p >> 3) & 3) * DH + (p >> 7) * 32 + (((p >> 5) & 3) << 3) + (p & 7);
}

__device__ __forceinline__ void mma16816(float& d0, float& d1, float& d2, float& d3,
                                         unsigned a0, unsigned a1, unsigned a2, unsigned a3,
                                         unsigned b0, unsigned b1) {
    asm volatile(
        "mma.sync.aligned.m16n8k16.row.col.f32.f16.f16.f32 "
        "{%0,%1,%2,%3}, {%4,%5,%6,%7}, {%8,%9}, {%0,%1,%2,%3};"
        : "+f"(d0), "+f"(d1), "+f"(d2), "+f"(d3)
        : "r"(a0), "r"(a1), "r"(a2), "r"(a3), "r"(b0), "r"(b1));
}

__device__ __forceinline__ float sigm(float x) { return 1.0f / (1.0f + __expf(-x)); }
__device__ __forceinline__ float tanh_a(float x) {
    x = fminf(fmaxf(x, -15.f), 15.f);
    float e = __expf(2.f * x);
    return (e - 1.f) / (e + 1.f);
}
__device__ __forceinline__ float lstm_cell(float zi, float zf, float zg, float zo, float& c) {
    float i = sigm(zi), f = sigm(zf), gg = tanh_a(zg), o = sigm(zo);
    c = fmaf(c, f, i * gg);
    return o * tanh_a(c);
}

// ---------------- cluster PTX helpers ----------------
__device__ __forceinline__ uint32_t smem_u32(const void* p) {
    uint32_t a;
    asm("{ .reg .u64 t; cvta.to.shared.u64 t, %1; cvt.u32.u64 %0, t; }" : "=r"(a) : "l"(p));
    return a;
}
__device__ __forceinline__ uint32_t cluster_rank() {
    uint32_t r; asm("mov.u32 %0, %%cluster_ctarank;" : "=r"(r)); return r;
}
__device__ __forceinline__ uint32_t mapa_u32(uint32_t local, uint32_t rank) {
    uint32_t a;
    asm("mapa.shared::cluster.u32 %0, %1, %2;" : "=r"(a) : "r"(local), "r"(rank));
    return a;
}
__device__ __forceinline__ void mbar_init(uint32_t a, uint32_t cnt) {
    asm volatile("mbarrier.init.shared.b64 [%0], %1;" :: "r"(a), "r"(cnt) : "memory");
}
__device__ __forceinline__ void mbar_arrive_expect_tx(uint32_t a, uint32_t tx) {
    asm volatile("mbarrier.arrive.expect_tx.shared.b64 _, [%0], %1;"
                 :: "r"(a), "r"(tx) : "memory");
}
__device__ __forceinline__ void mbar_wait(uint32_t a, int parity) {
    asm volatile(
        "{\n\t.reg .pred P;\n\t"
        "WL_%=:\n\t"
        "mbarrier.try_wait.parity.acquire.cta.shared::cta.b64 P, [%0], %1, 0x989680;\n\t"
        "@P bra WD_%=;\n\t"
        "bra WL_%=;\n\t"
        "WD_%=:\n\t}"
        :: "r"(a), "r"(parity) : "memory");
}
// 1KB SMEM->peer-SMEM bulk copy, tx-counted on the peer's mbarrier
__device__ __forceinline__ void bulk_s2s(uint32_t dst, uint32_t src, uint32_t bytes,
                                         uint32_t peer_mbar) {
    asm volatile(
        "cp.async.bulk.shared::cluster.shared::cta.mbarrier::complete_tx::bytes "
        "[%0], [%1], %2, [%3];"
        :: "r"(dst), "r"(src), "r"(bytes), "r"(peer_mbar) : "memory");
}
__device__ __forceinline__ void fence_proxy_async_cta() {
    asm volatile("fence.proxy.async.shared::cta;" ::: "memory");
}
__device__ __forceinline__ void cluster_sync_() {
    asm volatile("barrier.cluster.arrive.aligned;" ::: "memory");
    asm volatile("barrier.cluster.wait.aligned;" ::: "memory");
}

// ---------------- prep kernels ----------------
__global__ void prep_x_kernel(const float* __restrict__ x) {
    size_t idx = (size_t)blockIdx.x * 256 + threadIdx.x;
    int k = idx & 255;
    int m = (int)(idx >> 8);
    int t = m >> 7, b = m & 127;
    g_x_h[idx] = __float2half_rn(x[((size_t)b * TT + t) * DIN + k]);
}

__global__ void prep_w_kernel(const float* __restrict__ w_x2h, const float* __restrict__ b_x2h,
                              const float* __restrict__ w_h2h, const float* __restrict__ b_h2h) {
    int idx = blockIdx.x * 256 + threadIdx.x;   // 1,048,576 = 2048*512
    {
        int p = idx >> 9, k = idx & 511;
        g_wh[idx] = __float2half_rn(w_h2h[(size_t)k * G4 + gate_col(p)]);
    }
    if (idx < G4 * DIN) {
        int p = idx >> 8, k = idx & 255;
        g_wx[idx] = __float2half_rn(w_x2h[(size_t)k * G4 + gate_col(p)]);
    }
    if (idx < G4) {
        int gc = gate_col(idx);
        g_gbias[idx] = b_x2h[gc] + b_h2h[gc];
    }
}

// ---------------- GEMM1: xg = x @ wx + bias (fp16 out) ----------------
#define G1_SMEM ((128 * 264 + 64 * 264) * 2)
__global__ __launch_bounds__(256, 1) void gemm1_kernel() {
    extern __shared__ __half sm[];
    __half* x_sm = sm;                 // 128 x 264
    __half* w_sm = sm + 128 * 264;     // 64  x 264
    const int tid = threadIdx.x;
    const int m0 = blockIdx.y * 128, n0 = blockIdx.x * 64;

    const uint4* xs = (const uint4*)g_x_h;
    #pragma unroll 4
    for (int i = tid; i < 4096; i += 256) {
        int r = i >> 5, k8 = (i & 31) << 3;
        *(uint4*)&x_sm[r * 264 + k8] = xs[(size_t)(m0 + r) * 32 + (i & 31)];
    }
    const uint4* ws = (const uint4*)g_wx;
    #pragma unroll 4
    for (int i = tid; i < 2048; i += 256) {
        int c = i >> 5, k8 = (i & 31) << 3;
        *(uint4*)&w_sm[c * 264 + k8] = ws[(size_t)(n0 + c) * 32 + (i & 31)];
    }
    __syncthreads();

    const int w = tid >> 5, lane = tid & 31, g = lane >> 2, q = lane & 3;
    const int r0 = 16 * w + g;
    float acc[8][4];
    #pragma unroll
    for (int nt = 0; nt < 8; nt++) { acc[nt][0] = acc[nt][1] = acc[nt][2] = acc[nt][3] = 0.f; }

    #pragma unroll 4
    for (int kt = 0; kt < 16; kt++) {
        int k0 = kt * 16 + 2 * q;
        unsigned a0 = *(const unsigned*)&x_sm[r0 * 264 + k0];
        unsigned a1 = *(const unsigned*)&x_sm[(r0 + 8) * 264 + k0];
        unsigned a2 = *(const unsigned*)&x_sm[r0 * 264 + k0 + 8];
        unsigned a3 = *(const unsigned*)&x_sm[(r0 + 8) * 264 + k0 + 8];
        #pragma unroll
        for (int nt = 0; nt < 8; nt++) {
            unsigned b0 = *(const unsigned*)&w_sm[(8 * nt + g) * 264 + k0];
            unsigned b1 = *(const unsigned*)&w_sm[(8 * nt + g) * 264 + k0 + 8];
            mma16816(acc[nt][0], acc[nt][1], acc[nt][2], acc[nt][3], a0, a1, a2, a3, b0, b1);
        }
    }
    #pragma unroll
    for (int nt = 0; nt < 8; nt++) {
        int p = n0 + 8 * nt + 2 * q;
        float2 gb = *(const float2*)&g_gbias[p];
        *(__half2*)&g_xg[(size_t)(m0 + r0) * G4 + p] =
            __floats2half2_rn(acc[nt][0] + gb.x, acc[nt][1] + gb.y);
        *(__half2*)&g_xg[(size_t)(m0 + r0 + 8) * G4 + p] =
            __floats2half2_rn(acc[nt][2] + gb.x, acc[nt][3] + gb.y);
    }
}

// ---------------- persistent recurrent kernel ----------------
// 128 CTAs = 8 batch-group clusters x 16 col-group CTAs.
// Per step each CTA produces its 16x32 h chunk, stages it contiguously, and
// bulk-copies it (1KB) into all 16 peers' h_sm[chunk=own rank]; completion is
// counted by the peer's full[s] mbarrier (expect_tx = 16KB total).
//
// Parity is stateless: full[s] waited at step t is completing phase
// floor((t-1)/2), so parity = ((t-1)>>1) & 1.
//
// Buffer safety (no empty barriers):
//  - peer sends h(t) only AFTER its step t-1 MMA (done reading h_sm[(t-1)&1]);
//    our full[t&1] firing proves all peers finished reading buffer (t+1)&1,
//    so sends of h(t+1) into peers' h_sm[(t+1)&1] are safe.
//  - staging double-buffered: peer's h(t+2) bytes (which gate our step t+2)
//    require our h(t+1) chunk to have ARRIVED (copy completed), so rewriting
//    staging[t&1] at t+2 is safe.
//  - full[s] re-arm at step t precedes our h(t+1) send (syncthreads between),
//    and the earliest h(t+2) bytes transitively require that send.
#define W_BYTES   (128 * 520 * 2)              // 133120 (multiple of 1024)
#define H_OFF     W_BYTES                      // h_sm: [2][16 chunks][16][32] halves
#define H_BUF     16384
#define STG_OFF   (H_OFF + 2 * H_BUF)          // staging: [2][16][32] halves (2KB)
#define RED_OFF   (STG_OFF + 2048)             // [128][17] floats
#define MBAR_OFF  (RED_OFF + 128 * 17 * 4)     // full0 @ +0, full1 @ +8
#define REC_SMEM  (MBAR_OFF + 64)
#define HTX       16384

__global__ __launch_bounds__(256, 1) void rec_kernel() {
    extern __shared__ unsigned char smraw[];
    __half* w_sm = (__half*)smraw;                    // 128 x 520
    float*  red  = (float*)(smraw + RED_OFF);

    const uint32_t sbase = smem_u32(smraw);
    const uint32_t mb    = sbase + MBAR_OFF;

    const int tid = threadIdx.x;
    const int bg = blockIdx.x >> 4;
    const uint32_t cg = cluster_rank();
    const int w = tid >> 5, lane = tid & 31;
    const int g = lane >> 2, q = lane & 3;
    const int w4 = w & 3, kh = w >> 2;
    const int r0 = g, r1 = g + 8;

    // stationary weights -> smem (once)
    const uint4* ws = (const uint4*)(g_wh + (size_t)cg * 128 * DH);
    #pragma unroll 8
    for (int i = tid; i < 8192; i += 256) {
        int c = i >> 6, k8 = (i & 63) << 3;
        *(uint4*)&w_sm[c * 520 + k8] = ws[i];
    }

    if (tid == 0) {
        mbar_init(mb + 0, 1);                 // full0 (h at even t; first use t=2)
        mbar_init(mb + 8, 1);                 // full1 (h at odd t;  first use t=1)
        mbar_arrive_expect_tx(mb + 0, HTX);
        mbar_arrive_expect_tx(mb + 8, HTX);
        asm volatile("fence.mbarrier_init.release.cluster;" ::: "memory");
    }
    __syncthreads();
    cluster_sync_();

    // thread tid<16 talks to peer rank 'tid'
    uint32_t peer_base = 0;
    if (tid < CLSZ) peer_base = mapa_u32(sbase, (uint32_t)tid);

    float c00 = 0.f, c01 = 0.f, c10 = 0.f, c11 = 0.f;

    for (int t = 0; t < TT; t++) {
        const int s = t & 1;

        // xg prefetch (warps 0-3), fp16 — in flight during the wait
        float2 xf0[4], xf1[4];
        if (kh == 0) {
            const __half* x0 = g_xg + (size_t)(t * BB + bg * 16 + r0) * G4
                               + cg * 128 + w4 * 32 + 2 * q;
            const __half* x1 = x0 + (size_t)8 * G4;
            #pragma unroll
            for (int nt = 0; nt < 4; nt++) {
                __half2 u0 = __ldg((const __half2*)(x0 + nt * 8));
                __half2 u1 = __ldg((const __half2*)(x1 + nt * 8));
                xf0[nt] = __half22float2(u0);
                xf1[nt] = __half22float2(u1);
            }
        }

        float acc[4][4];
        #pragma unroll
        for (int nt = 0; nt < 4; nt++) { acc[nt][0] = acc[nt][1] = acc[nt][2] = acc[nt][3] = 0.f; }

        if (t > 0) {
            // wait: all 16 peer chunks landed in h_sm[s]; re-arm for use at t+2
            if (tid == 0) {
                mbar_wait(mb + s * 8, ((t - 1) >> 1) & 1);
                mbar_arrive_expect_tx(mb + s * 8, HTX);
            }
            __syncthreads();

            // gates += h @ W  (A from chunked h_sm: [chunk][16 rows][32 units])
            const __half* hb = (const __half*)(smraw + H_OFF) + s * (H_BUF / 2);
            #pragma unroll
            for (int kt = 0; kt < 16; kt++) {
                int k0 = kh * 256 + kt * 16 + 2 * q;
                const __half* hc = hb + ((k0 >> 5) << 9) + (k0 & 31);
                unsigned a0 = *(const unsigned*)&hc[r0 * 32];
                unsigned a1 = *(const unsigned*)&hc[r1 * 32];
                unsigned a2 = *(const unsigned*)&hc[r0 * 32 + 8];
                unsigned a3 = *(const unsigned*)&hc[r1 * 32 + 8];
                #pragma unroll
                for (int nt = 0; nt < 4; nt++) {
                    const __half* wb = &w_sm[(w4 * 32 + nt * 8 + g) * 520 + k0];
                    unsigned b0 = *(const unsigned*)wb;
                    unsigned b1 = *(const unsigned*)(wb + 8);
                    mma16816(acc[nt][0], acc[nt][1], acc[nt][2], acc[nt][3], a0, a1, a2, a3, b0, b1);
                }
            }

            // split-K reduction: warps 4-7 hand partials to warps 0-3
            if (kh == 1) {
                float* rp = red + (w4 * 32 + lane) * 17;
                #pragma unroll
                for (int nt = 0; nt < 4; nt++) {
                    #pragma unroll
                    for (int e = 0; e < 4; e++) rp[nt * 4 + e] = acc[nt][e];
                }
            }
            __syncthreads();
            if (kh == 0) {
                const float* rp = red + (w4 * 32 + lane) * 17;
                #pragma unroll
                for (int nt = 0; nt < 4; nt++) {
                    #pragma unroll
                    for (int e = 0; e < 4; e++) acc[nt][e] += rp[nt * 4 + e];
                }
            }
        }

        if (kh == 0) {
            float h00 = lstm_cell(acc[0][0] + xf0[0].x, acc[1][0] + xf0[1].x,
                                  acc[2][0] + xf0[2].x, acc[3][0] + xf0[3].x, c00);
            float h01 = lstm_cell(acc[0][1] + xf0[0].y, acc[1][1] + xf0[1].y,
                                  acc[2][1] + xf0[2].y, acc[3][1] + xf0[3].y, c01);
            float h10 = lstm_cell(acc[0][2] + xf1[0].x, acc[1][2] + xf1[1].x,
                                  acc[2][2] + xf1[2].x, acc[3][2] + xf1[3].x, c10);
            float h11 = lstm_cell(acc[0][3] + xf1[0].y, acc[1][3] + xf1[1].y,
                                  acc[2][3] + xf1[2].y, acc[3][3] + xf1[3].y, c11);

            if (t < TT - 1) {
                // stage own 16x32 chunk (contiguous 1KB)
                __half* stg = (__half*)(smraw + STG_OFF) + (t & 1) * 512;
                int u = w4 * 8 + 2 * q;
                *(__half2*)&stg[r0 * 32 + u] = __floats2half2_rn(h00, h01);
                *(__half2*)&stg[r1 * 32 + u] = __floats2half2_rn(h10, h11);
            } else {
                int row0 = bg * 16 + r0, row1 = row0 + 8;
                int hoff = (int)cg * 32 + w4 * 8 + 2 * q;
                *(float2*)&g_hlast[row0 * DH + hoff] = make_float2(h00, h01);
                *(float2*)&g_hlast[row1 * DH + hoff] = make_float2(h10, h11);
            }
        }

        if (t < TT - 1) {
            __syncthreads();   // staging complete; re-arm visible cluster-wide
            if (tid < CLSZ) {
                fence_proxy_async_cta();
                const uint32_t src = sbase + STG_OFF + (uint32_t)(t & 1) * 1024;
                const uint32_t dst = peer_base + H_OFF
                                     + (uint32_t)((t + 1) & 1) * H_BUF + cg * 1024;
                const uint32_t pmb = peer_base + MBAR_OFF + (uint32_t)((t + 1) & 1) * 8;
                bulk_s2s(dst, src, 1024, pmb);
            }
        }
    }
    cluster_sync_();
}

// ---------------- final FC ----------------
__global__ void fc_kernel(const float* __restrict__ w_fc, const float* __restrict__ b_fc,
                          float* __restrict__ out) {
    __shared__ float hs[DH];
    int b = blockIdx.x, o = threadIdx.x;
    for (int i = o; i < DH; i += 256) hs[i] = g_hlast[b * DH + i];
    __syncthreads();
    float acc = b_fc[o];
    #pragma unroll 8
    for (int k = 0; k < DH; k++) acc = fmaf(hs[k], w_fc[(size_t)k * DOUT + o], acc);
    out[b * DOUT + o] = acc;
}

// ---------------- launch ----------------
extern "C" void kernel_launch(void* const* d_in, const int* in_sizes, int n_in,
                              void* d_out, int out_size) {
    (void)in_sizes; (void)n_in; (void)out_size;
    const float* x     = (const float*)d_in[0];
    const float* w_x2h = (const float*)d_in[1];
    const float* b_x2h = (const float*)d_in[2];
    const float* w_h2h = (const float*)d_in[3];
    const float* b_h2h = (const float*)d_in[4];
    const float* w_fc  = (const float*)d_in[5];
    const float* b_fc  = (const float*)d_in[6];
    float* out = (float*)d_out;

    cudaFuncSetAttribute(gemm1_kernel, cudaFuncAttributeMaxDynamicSharedMemorySize, G1_SMEM);
    cudaFuncSetAttribute(rec_kernel,   cudaFuncAttributeMaxDynamicSharedMemorySize, REC_SMEM);
    cudaFuncSetAttribute(rec_kernel,   cudaFuncAttributeNonPortableClusterSizeAllowed, 1);

    prep_x_kernel<<<65536, 256>>>(x);
    prep_w_kernel<<<4096, 256>>>(w_x2h, b_x2h, w_h2h, b_h2h);
    gemm1_kernel<<<dim3(32, 512), 256, G1_SMEM>>>();

    cudaLaunchConfig_t cfg = {};
    cfg.gridDim = dim3(RCTA, 1, 1);
    cfg.blockDim = dim3(256, 1, 1);
    cfg.dynamicSmemBytes = REC_SMEM;
    cfg.stream = 0;
    cudaLaunchAttribute at[1];
    at[0].id = cudaLaunchAttributeClusterDimension;
    at[0].val.clusterDim.x = CLSZ; at[0].val.clusterDim.y = 1; at[0].val.clusterDim.z = 1;
    cfg.attrs = at; cfg.numAttrs = 1;
    cudaLaunchKernelEx(&cfg, rec_kernel);

    fc_kernel<<<BB, 256>>>(w_fc, b_fc, out);
}

// round 8
// speedup vs baseline: 3.1707x; 1.8057x over previous
#include <cuda_runtime.h>
#include <cuda_fp16.h>
#include <cstdint>

// Problem dims
#define BB    128
#define TT    512
#define DIN   256
#define DH    512
#define G4    2048        // 4*DH
#define DOUT  256
#define RCTA  128         // 8 batch groups x 16 col groups
#define GRPSZ 16

// ---------------- static device scratch ----------------
__device__ __half g_x_h[(size_t)BB * TT * DIN];       // x fp16, [m=t*128+b][k]
__device__ __half g_wx [(size_t)G4 * DIN];            // w_x2h permuted, [p][k]
__device__ __half g_wh [(size_t)G4 * DH];             // w_h2h permuted, [p][k]
__device__ float  g_gbias[G4];                        // permuted biases
__device__ __half g_xg [(size_t)BB * TT * G4];        // xg fp16, [m][p]
__device__ __half g_hbuf[2][BB * DH];                 // double-buffered h (fp16, L2)
__device__ float  g_hlast[BB * DH];                   // final h fp32
__device__ int    g_flags[RCTA];

// permuted gate column: p = cg*128 + w*16 + q*4 + u
//   cg = p>>7, w = (p>>4)&7 (warp), q = (p>>2)&3 (gate), u = p&3 (unit)
// original col = q*512 + (hidden unit = cg*32 + w*4 + u)
__device__ __forceinline__ int gate_col(int p) {
    return ((p >> 2) & 3) * DH + (p >> 7) * 32 + (((p >> 4) & 7) << 2) + (p & 3);
}

__device__ __forceinline__ void mma16816(float& d0, float& d1, float& d2, float& d3,
                                         unsigned a0, unsigned a1, unsigned a2, unsigned a3,
                                         unsigned b0, unsigned b1) {
    asm volatile(
        "mma.sync.aligned.m16n8k16.row.col.f32.f16.f16.f32 "
        "{%0,%1,%2,%3}, {%4,%5,%6,%7}, {%8,%9}, {%0,%1,%2,%3};"
        : "+f"(d0), "+f"(d1), "+f"(d2), "+f"(d3)
        : "r"(a0), "r"(a1), "r"(a2), "r"(a3), "r"(b0), "r"(b1));
}

__device__ __forceinline__ void ldsm_x4(unsigned& a0, unsigned& a1, unsigned& a2, unsigned& a3,
                                        uint32_t addr) {
    asm volatile("ldmatrix.sync.aligned.m8n8.x4.shared.b16 {%0,%1,%2,%3}, [%4];"
                 : "=r"(a0), "=r"(a1), "=r"(a2), "=r"(a3) : "r"(addr));
}

__device__ __forceinline__ uint32_t smem_u32(const void* p) {
    uint32_t a;
    asm("{ .reg .u64 t; cvta.to.shared.u64 t, %1; cvt.u32.u64 %0, t; }" : "=r"(a) : "l"(p));
    return a;
}

__device__ __forceinline__ void stg_cg_u16(__half* p, __half v) {
    unsigned short s = __half_as_ushort(v);
    asm volatile("st.global.cg.u16 [%0], %1;" :: "l"(p), "h"(s) : "memory");
}

__device__ __forceinline__ float sigm(float x) { return 1.0f / (1.0f + __expf(-x)); }
__device__ __forceinline__ float tanh_a(float x) {
    x = fminf(fmaxf(x, -15.f), 15.f);
    float e = __expf(2.f * x);
    return (e - 1.f) / (e + 1.f);
}
__device__ __forceinline__ float lstm_cell(float zi, float zf, float zg, float zo, float& c) {
    float i = sigm(zi), f = sigm(zf), gg = tanh_a(zg), o = sigm(zo);
    c = fmaf(c, f, i * gg);
    return o * tanh_a(c);
}

// ---------------- prep kernels ----------------
__global__ void prep_x_kernel(const float* __restrict__ x) {
    size_t idx = (size_t)blockIdx.x * 256 + threadIdx.x;
    int k = idx & 255;
    int m = (int)(idx >> 8);
    int t = m >> 7, b = m & 127;
    g_x_h[idx] = __float2half_rn(x[((size_t)b * TT + t) * DIN + k]);
}

__global__ void prep_w_kernel(const float* __restrict__ w_x2h, const float* __restrict__ b_x2h,
                              const float* __restrict__ w_h2h, const float* __restrict__ b_h2h) {
    int idx = blockIdx.x * 256 + threadIdx.x;   // 1,048,576 = 2048*512
    {
        int p = idx >> 9, k = idx & 511;
        g_wh[idx] = __float2half_rn(w_h2h[(size_t)k * G4 + gate_col(p)]);
    }
    if (idx < G4 * DIN) {
        int p = idx >> 8, k = idx & 255;
        g_wx[idx] = __float2half_rn(w_x2h[(size_t)k * G4 + gate_col(p)]);
    }
    if (idx < G4) {
        int gc = gate_col(idx);
        g_gbias[idx] = b_x2h[gc] + b_h2h[gc];
    }
    if (idx < RCTA) g_flags[idx] = 0;
}

// ---------------- GEMM1: xg = x @ wx + bias (fp16 out) ----------------
#define G1_SMEM ((128 * 264 + 64 * 264) * 2)
__global__ __launch_bounds__(256, 1) void gemm1_kernel() {
    extern __shared__ __half sm[];
    __half* x_sm = sm;                 // 128 x 264
    __half* w_sm = sm + 128 * 264;     // 64  x 264
    const int tid = threadIdx.x;
    const int m0 = blockIdx.y * 128, n0 = blockIdx.x * 64;

    const uint4* xs = (const uint4*)g_x_h;
    #pragma unroll 4
    for (int i = tid; i < 4096; i += 256) {
        int r = i >> 5, k8 = (i & 31) << 3;
        *(uint4*)&x_sm[r * 264 + k8] = xs[(size_t)(m0 + r) * 32 + (i & 31)];
    }
    const uint4* ws = (const uint4*)g_wx;
    #pragma unroll 4
    for (int i = tid; i < 2048; i += 256) {
        int c = i >> 5, k8 = (i & 31) << 3;
        *(uint4*)&w_sm[c * 264 + k8] = ws[(size_t)(n0 + c) * 32 + (i & 31)];
    }
    __syncthreads();

    const int w = tid >> 5, lane = tid & 31, g = lane >> 2, q = lane & 3;
    const int r0 = 16 * w + g;
    float acc[8][4];
    #pragma unroll
    for (int nt = 0; nt < 8; nt++) { acc[nt][0] = acc[nt][1] = acc[nt][2] = acc[nt][3] = 0.f; }

    #pragma unroll 4
    for (int kt = 0; kt < 16; kt++) {
        int k0 = kt * 16 + 2 * q;
        unsigned a0 = *(const unsigned*)&x_sm[r0 * 264 + k0];
        unsigned a1 = *(const unsigned*)&x_sm[(r0 + 8) * 264 + k0];
        unsigned a2 = *(const unsigned*)&x_sm[r0 * 264 + k0 + 8];
        unsigned a3 = *(const unsigned*)&x_sm[(r0 + 8) * 264 + k0 + 8];
        #pragma unroll
        for (int nt = 0; nt < 8; nt++) {
            unsigned b0 = *(const unsigned*)&w_sm[(8 * nt + g) * 264 + k0];
            unsigned b1 = *(const unsigned*)&w_sm[(8 * nt + g) * 264 + k0 + 8];
            mma16816(acc[nt][0], acc[nt][1], acc[nt][2], acc[nt][3], a0, a1, a2, a3, b0, b1);
        }
    }
    #pragma unroll
    for (int nt = 0; nt < 8; nt++) {
        int p = n0 + 8 * nt + 2 * q;
        float2 gb = *(const float2*)&g_gbias[p];
        *(__half2*)&g_xg[(size_t)(m0 + r0) * G4 + p] =
            __floats2half2_rn(acc[nt][0] + gb.x, acc[nt][1] + gb.y);
        *(__half2*)&g_xg[(size_t)(m0 + r0 + 8) * G4 + p] =
            __floats2half2_rn(acc[nt][2] + gb.x, acc[nt][3] + gb.y);
    }
}

// ---------------- persistent recurrent kernel ----------------
// 128 CTAs = 8 batch groups x 16 col groups. Weights register-resident
// (128 regs/thread). Exchange: L2 data + volatile flag poll (R2 mechanism),
// per-warp chunked: warp w polls producers {2w,2w+1} and loads their 2KB.
__global__ __launch_bounds__(256, 1) void rec_kernel() {
    __shared__ __half h_sm[16 * 520];      // A tile: 16 rows x 512 (+8 pad)

    const int tid = threadIdx.x;
    const int j = blockIdx.x;
    const int bg = j >> 4, cg = j & 15;
    const int w = tid >> 5, lane = tid & 31;
    const int g = lane >> 2, tq = lane & 3;
    const int b = tq >> 1;

    // -------- one-time: B fragments -> registers (128 regs) --------
    // breg[nt*64 + kt*2 + {0,1}] : W row (cg*128 + w*16 + nt*8 + g), k = kt*16+2tq (+8)
    unsigned breg[128];
    #pragma unroll
    for (int nt = 0; nt < 2; nt++) {
        const __half* wrow = g_wh + (size_t)(cg * 128 + w * 16 + nt * 8 + g) * DH + 2 * tq;
        #pragma unroll
        for (int kt = 0; kt < 32; kt++) {
            breg[nt * 64 + kt * 2]     = *(const unsigned*)(wrow + kt * 16);
            breg[nt * 64 + kt * 2 + 1] = *(const unsigned*)(wrow + kt * 16 + 8);
        }
    }

    // ldmatrix per-lane base: groups of 8 lanes -> (rows 0-7/8-15) x (k +0/+8)
    const uint32_t hbase = smem_u32(h_sm);
    const int grp = lane >> 3;
    const uint32_t abase = hbase + (uint32_t)((((grp & 1) * 8 + (lane & 7)) * 520
                                               + (grp >> 1) * 8) * 2);

    float c0 = 0.f, c1 = 0.f;      // cell state: 2 rows x 1 unit per thread

    for (int t = 0; t < TT; t++) {
        // xg prefetch (fp16), in flight during the wait
        const __half* xrow0 = g_xg + (size_t)(t * BB + bg * 16 + g) * G4
                              + cg * 128 + w * 16 + 2 * tq;
        const __half* xrow1 = xrow0 + (size_t)8 * G4;
        __half2 x00 = __ldg((const __half2*)xrow0);
        __half2 x01 = __ldg((const __half2*)(xrow0 + 8));
        __half2 x10 = __ldg((const __half2*)xrow1);
        __half2 x11 = __ldg((const __half2*)(xrow1 + 8));

        float acc[2][4];
        acc[0][0] = acc[0][1] = acc[0][2] = acc[0][3] = 0.f;
        acc[1][0] = acc[1][1] = acc[1][2] = acc[1][3] = 0.f;

        if (t > 0) {
            // per-warp: wait for producers 2w, 2w+1; load their chunks (2KB)
            if (lane < 2) {
                volatile int* fl = g_flags + bg * 16 + 2 * w + lane;
                while (*fl < t) { }
            }
            __syncwarp();
            asm volatile("membar.gl;" ::: "memory");

            const uint4* hsrc = (const uint4*)(g_hbuf[t & 1]);
            const int r = lane >> 1, hh = lane & 1;
            #pragma unroll
            for (int ci = 0; ci < 2; ci++) {
                int c = 2 * w + ci;
                #pragma unroll
                for (int jj = 0; jj < 2; jj++) {
                    uint4 v = __ldcg(hsrc + (size_t)(bg * 16 + r) * 64 + c * 4 + hh * 2 + jj);
                    *(uint4*)&h_sm[r * 520 + c * 32 + (hh * 2 + jj) * 8] = v;
                }
            }
            __syncthreads();

            // gates += h @ W : 32 kt x 2 HMMA, A via ldmatrix, B in regs
            #pragma unroll
            for (int kt = 0; kt < 32; kt++) {
                unsigned a0, a1, a2, a3;
                ldsm_x4(a0, a1, a2, a3, abase + kt * 32);
                mma16816(acc[0][0], acc[0][1], acc[0][2], acc[0][3],
                         a0, a1, a2, a3, breg[kt * 2], breg[kt * 2 + 1]);
                mma16816(acc[1][0], acc[1][1], acc[1][2], acc[1][3],
                         a0, a1, a2, a3, breg[64 + kt * 2], breg[64 + kt * 2 + 1]);
            }
        }

        // add xg (acc cols c = nt*8 + 2tq + e; j = row*2 + e)
        {
            float2 f;
            f = __half22float2(x00); acc[0][0] += f.x; acc[0][1] += f.y;
            f = __half22float2(x01); acc[1][0] += f.x; acc[1][1] += f.y;
            f = __half22float2(x10); acc[0][2] += f.x; acc[0][3] += f.y;
            f = __half22float2(x11); acc[1][2] += f.x; acc[1][3] += f.y;
        }

        // gate exchange: pair (tq, tq^2); keep e=b slot, send e=1-b slot
        float r00 = __shfl_xor_sync(0xffffffffu, acc[0][1 - b], 2);  // nt0 row0
        float r01 = __shfl_xor_sync(0xffffffffu, acc[0][3 - b], 2);  // nt0 row1
        float r10 = __shfl_xor_sync(0xffffffffu, acc[1][1 - b], 2);  // nt1 row0
        float r11 = __shfl_xor_sync(0xffffffffu, acc[1][3 - b], 2);  // nt1 row1
        float o00 = acc[0][b],     o01 = acc[0][2 + b];
        float o10 = acc[1][b],     o11 = acc[1][2 + b];

        // own gates q = 2nt+b, recv gates q = 2nt+1-b  (i=0,f=1,g=2,o=3)
        float zi0 = b ? r00 : o00,  zf0 = b ? o00 : r00;
        float zg0 = b ? r10 : o10,  zo0 = b ? o10 : r10;
        float zi1 = b ? r01 : o01,  zf1 = b ? o01 : r01;
        float zg1 = b ? r11 : o11,  zo1 = b ? o11 : r11;

        float h0 = lstm_cell(zi0, zf0, zg0, zo0, c0);
        float h1 = lstm_cell(zi1, zf1, zg1, zo1, c1);

        const int U = cg * 32 + w * 4 + (((tq & 1) << 1) | b);
        const int row0 = bg * 16 + g, row1 = row0 + 8;

        if (t < TT - 1) {
            __half* hd = g_hbuf[(t + 1) & 1];
            stg_cg_u16(hd + (size_t)row0 * DH + U, __float2half_rn(h0));
            stg_cg_u16(hd + (size_t)row1 * DH + U, __float2half_rn(h1));
            __threadfence();
            __syncthreads();
            if (tid == 0) atomicExch(&g_flags[j], t + 1);
        } else {
            g_hlast[(size_t)row0 * DH + U] = h0;
            g_hlast[(size_t)row1 * DH + U] = h1;
        }
    }
}

// ---------------- final FC ----------------
__global__ void fc_kernel(const float* __restrict__ w_fc, const float* __restrict__ b_fc,
                          float* __restrict__ out) {
    __shared__ float hs[DH];
    int bb = blockIdx.x, o = threadIdx.x;
    for (int i = o; i < DH; i += 256) hs[i] = g_hlast[bb * DH + i];
    __syncthreads();
    float acc = b_fc[o];
    #pragma unroll 8
    for (int k = 0; k < DH; k++) acc = fmaf(hs[k], w_fc[(size_t)k * DOUT + o], acc);
    out[bb * DOUT + o] = acc;
}

// ---------------- launch ----------------
extern "C" void kernel_launch(void* const* d_in, const int* in_sizes, int n_in,
                              void* d_out, int out_size) {
    (void)in_sizes; (void)n_in; (void)out_size;
    const float* x     = (const float*)d_in[0];
    const float* w_x2h = (const float*)d_in[1];
    const float* b_x2h = (const float*)d_in[2];
    const float* w_h2h = (const float*)d_in[3];
    const float* b_h2h = (const float*)d_in[4];
    const float* w_fc  = (const float*)d_in[5];
    const float* b_fc  = (const float*)d_in[6];
    float* out = (float*)d_out;

    cudaFuncSetAttribute(gemm1_kernel, cudaFuncAttributeMaxDynamicSharedMemorySize, G1_SMEM);

    prep_x_kernel<<<65536, 256>>>(x);
    prep_w_kernel<<<4096, 256>>>(w_x2h, b_x2h, w_h2h, b_h2h);
    gemm1_kernel<<<dim3(32, 512), 256, G1_SMEM>>>();
    rec_kernel<<<RCTA, 256>>>();
    fc_kernel<<<BB, 256>>>(w_fc, b_fc, out);
}